// round 3
// baseline (speedup 1.0000x reference)
#include <cuda_runtime.h>
#include <cuda_bf16.h>

// VolumeRenderer: NeRF alpha-compositing.
//   delta_i = depth_{i+1} - depth_i (border 1e10 at i=191)
//   alpha_i = 1 - exp(-relu(sigma_i) * delta_i)
//   surv_i  = exp(-relu(sigma_i)*delta_i) + 1e-10
//   T_i     = exclusive cumprod(surv)
//   w_i     = alpha_i * T_i
//   color   = sum_i sigmoid(rgb_i) * w_i ; depth_out = sum w_i d_i ; acc = sum w_i
//
// Output layout (tuple flattened): color[3N] | depth[N] | acc[N] | weights[192N]
//
// One warp per ray; 6 samples per lane (blocked). Exclusive cumprod via
// warp multiplicative scan of per-thread local products.

#define NS   192
#define SPT  6
#define EPSV 1e-10f
#define BORDER 1e10f

__device__ __forceinline__ float fsigmoid(float x) {
    return __fdividef(1.0f, 1.0f + __expf(-x));
}

__global__ void __launch_bounds__(256)
vr_kernel(const float* __restrict__ depth,
          const float* __restrict__ rgb,
          const float* __restrict__ sigma,
          float* __restrict__ out,
          int n_rays)
{
    const int gwarp = (blockIdx.x * blockDim.x + threadIdx.x) >> 5;
    if (gwarp >= n_rays) return;
    const int lane = threadIdx.x & 31;
    const long base = (long)gwarp * NS;

    // ---- load depth (6 floats = 3x float2, 8B-aligned) ----
    float d[SPT];
    {
        const float2* dp = reinterpret_cast<const float2*>(depth + base + lane * SPT);
        #pragma unroll
        for (int j = 0; j < 3; j++) { float2 v = dp[j]; d[2*j] = v.x; d[2*j+1] = v.y; }
    }
    // ---- load sigma ----
    float sg[SPT];
    {
        const float2* sp = reinterpret_cast<const float2*>(sigma + base + lane * SPT);
        #pragma unroll
        for (int j = 0; j < 3; j++) { float2 v = sp[j]; sg[2*j] = v.x; sg[2*j+1] = v.y; }
    }

    // next lane's first depth (needed for this lane's last delta)
    const float dnext = __shfl_down_sync(0xffffffffu, d[0], 1);

    // ---- alpha / survival, local product ----
    float e[SPT];
    float p = 1.0f;
    #pragma unroll
    for (int j = 0; j < SPT; j++) {
        float dn = (j < SPT - 1) ? d[j + 1] : dnext;
        float delta = dn - d[j];
        if (lane == 31 && j == SPT - 1) delta = BORDER;  // pad last sample
        float s = fmaxf(sg[j], 0.0f);
        float ex = __expf(-s * delta);
        e[j] = ex;
        p *= (ex + EPSV);
    }

    // ---- warp inclusive multiplicative scan of per-thread products ----
    float incl = p;
    #pragma unroll
    for (int off = 1; off < 32; off <<= 1) {
        float v = __shfl_up_sync(0xffffffffu, incl, off);
        if (lane >= off) incl *= v;
    }
    float t = __shfl_up_sync(0xffffffffu, incl, 1);  // exclusive prefix
    if (lane == 0) t = 1.0f;

    // ---- rgb loads (18 floats = 9x float2, 8B-aligned) ----
    float r[18];
    {
        const float2* rp = reinterpret_cast<const float2*>(rgb + (base + lane * SPT) * 3);
        #pragma unroll
        for (int j = 0; j < 9; j++) { float2 v = rp[j]; r[2*j] = v.x; r[2*j+1] = v.y; }
    }

    // ---- weights + reductions ----
    float w[SPT];
    float acc = 0.0f, dep = 0.0f, c0 = 0.0f, c1 = 0.0f, c2 = 0.0f;
    #pragma unroll
    for (int j = 0; j < SPT; j++) {
        float wj = (1.0f - e[j]) * t;   // alpha * T
        t *= (e[j] + EPSV);             // advance transmittance
        w[j] = wj;
        acc += wj;
        dep = fmaf(wj, d[j], dep);
        c0 = fmaf(wj, fsigmoid(r[3*j + 0]), c0);
        c1 = fmaf(wj, fsigmoid(r[3*j + 1]), c1);
        c2 = fmaf(wj, fsigmoid(r[3*j + 2]), c2);
    }

    // ---- write weights (6 floats = 3x float2) ----
    {
        float2* wo = reinterpret_cast<float2*>(out + (long)5 * n_rays + base + lane * SPT);
        #pragma unroll
        for (int j = 0; j < 3; j++) wo[j] = make_float2(w[2*j], w[2*j+1]);
    }

    // ---- warp reduce 5 scalars ----
    #pragma unroll
    for (int off = 16; off; off >>= 1) {
        acc += __shfl_xor_sync(0xffffffffu, acc, off);
        dep += __shfl_xor_sync(0xffffffffu, dep, off);
        c0  += __shfl_xor_sync(0xffffffffu, c0,  off);
        c1  += __shfl_xor_sync(0xffffffffu, c1,  off);
        c2  += __shfl_xor_sync(0xffffffffu, c2,  off);
    }
    if (lane == 0) {
        out[(long)gwarp * 3 + 0] = c0;
        out[(long)gwarp * 3 + 1] = c1;
        out[(long)gwarp * 3 + 2] = c2;
        out[(long)3 * n_rays + gwarp] = dep;
        out[(long)4 * n_rays + gwarp] = acc;
    }
}

extern "C" void kernel_launch(void* const* d_in, const int* in_sizes, int n_in,
                              void* d_out, int out_size)
{
    const float* depth = (const float*)d_in[0];
    const float* rgb   = (const float*)d_in[1];
    const float* sigma = (const float*)d_in[2];
    float* out = (float*)d_out;

    const int n_rays = in_sizes[0] / NS;   // depth has N*192 elements
    const int threads = 256;               // 8 warps = 8 rays per block
    const int blocks = (n_rays + (threads / 32) - 1) / (threads / 32);
    vr_kernel<<<blocks, threads>>>(depth, rgb, sigma, out, n_rays);
}